// round 11
// baseline (speedup 1.0000x reference)
#include <cuda_runtime.h>
#include <cuda_fp16.h>
#include <cstdint>

// ===========================================================================
// MoE (B=8192, H=O=4096, E=8, top-2 softmax), fp16 warp MMA, fp32 accum.
// R11: GEMM = R8 (crossbar-roofline floor, ~77% tensor, unchanged).
//      Pre-passes fused: gating+x->fp16 and W transpose/convert run
//      CONCURRENTLY in one launch (z-plane dispatch); g_count zeroed via
//      cudaMemsetAsync on the device symbol (one less launch).
// ===========================================================================

#define MAX_B   8192
#define NEXP    8
#define HDIM    4096
#define ODIM    4096

#define MT      128
#define NT      128
#define KC      64
#define KSTAGES (HDIM / KC)     // 64
#define NSTAGE  3

// SMEM layout (GEMM)
#define SM_ENT      0           // 128 ints
#define SM_W        512         // 128 floats
#define SM_TILES    1024
#define ST_A        0           // 16KB
#define ST_B        16384       // 16KB
#define STAGE_BYTES 32768
#define SMEM_TOTAL  (SM_TILES + NSTAGE * STAGE_BYTES)   // 99328

// ---------------------------------------------------------------------------
__device__ int   g_count[NEXP];
__device__ int   g_list [NEXP * MAX_B];
__device__ float g_wlist[NEXP * MAX_B];
__device__ __half g_xh [(size_t)MAX_B * HDIM];
__device__ __half g_whT[(size_t)NEXP * ODIM * HDIM];   // [e][n][k]

// ---------------------------------------------------------------------------
__device__ __forceinline__ uint32_t smem_u32(const void* p) {
    uint32_t a;
    asm("{ .reg .u64 t; cvta.to.shared.u64 t, %1; cvt.u32.u64 %0, t; }"
        : "=r"(a) : "l"(p));
    return a;
}
__device__ __forceinline__ void cp_async16(uint32_t dst, const void* src) {
    asm volatile("cp.async.cg.shared.global [%0], [%1], 16;"
                 :: "r"(dst), "l"(src) : "memory");
}
#define CP_COMMIT() asm volatile("cp.async.commit_group;" ::: "memory")
#define CP_WAIT1()  asm volatile("cp.async.wait_group 1;" ::: "memory")

#define SWZ(x) ((x) ^ (((x) >> 3) & 0x70))

__device__ __forceinline__ void ldsm4(uint32_t r[4], uint32_t addr) {
    asm volatile("ldmatrix.sync.aligned.m8n8.x4.shared.b16 {%0,%1,%2,%3}, [%4];"
                 : "=r"(r[0]), "=r"(r[1]), "=r"(r[2]), "=r"(r[3]) : "r"(addr));
}
__device__ __forceinline__ void hmma(float c[4], const uint32_t a[4],
                                     uint32_t b0, uint32_t b1) {
    asm volatile(
        "mma.sync.aligned.m16n8k16.row.col.f32.f16.f16.f32 "
        "{%0,%1,%2,%3}, {%4,%5,%6,%7}, {%8,%9}, {%0,%1,%2,%3};"
        : "+f"(c[0]), "+f"(c[1]), "+f"(c[2]), "+f"(c[3])
        : "r"(a[0]), "r"(a[1]), "r"(a[2]), "r"(a[3]), "r"(b0), "r"(b1));
}

// ---------------------------------------------------------------------------
// Fused pre-pass. Grid (64, 64, 9), 256 threads.
//   z in [0,8):  W[e=z][k][n] fp32 -> g_whT[e][n][k] fp16  (64k x 64n tile)
//   z == 8:      gating (blocks with flat id < B/8), fused x -> fp16
// Both halves are independent (disjoint outputs); co-scheduling overlaps the
// DRAM-bound convert with the latency-bound gating.
__global__ __launch_bounds__(256)
void prepass_kernel(const float* __restrict__ x,
                    const float* __restrict__ gw,
                    const float* __restrict__ W, int B)
{
    __shared__ float tile[64][65];
    const int tid = threadIdx.x;

    if (blockIdx.z < NEXP) {
        // ---------------- convert_w (identical math to R10) ----------------
        const int n0 = blockIdx.x * 64;
        const int k0 = blockIdx.y * 64;
        const size_t eoff = (size_t)blockIdx.z * HDIM * ODIM;

#pragma unroll
        for (int rep = 0; rep < 4; rep++) {
            int idx = rep * 256 + tid;
            int kr = idx >> 4, c = idx & 15;
            float4 v = *reinterpret_cast<const float4*>(
                W + eoff + (size_t)(k0 + kr) * ODIM + n0 + c * 4);
            tile[kr][c * 4 + 0] = v.x;
            tile[kr][c * 4 + 1] = v.y;
            tile[kr][c * 4 + 2] = v.z;
            tile[kr][c * 4 + 3] = v.w;
        }
        __syncthreads();

        const int u = tid & 7;
#pragma unroll
        for (int rep = 0; rep < 2; rep++) {
            int n = (tid >> 3) + rep * 32;
            __half2 h[4];
#pragma unroll
            for (int j = 0; j < 4; j++) {
                float v0 = tile[u * 8 + 2 * j][n];
                float v1 = tile[u * 8 + 2 * j + 1][n];
                h[j] = __floats2half2_rn(v0, v1);
            }
            *reinterpret_cast<uint4*>(
                g_whT + eoff + (size_t)(n0 + n) * HDIM + k0 + u * 8)
                = *reinterpret_cast<uint4*>(h);
        }
        return;
    }

    // ---------------- gating (identical math/order to R10) ----------------
    const int blk = blockIdx.x + blockIdx.y * 64;     // flat block id
    if (blk >= (B + 7) / 8) return;

    const int warp  = tid >> 5;
    const int lane  = tid & 31;
    const int token = blk * 8 + warp;
    if (token >= B) return;

    const float* xr = x + (size_t)token * HDIM;
    __half* xh = g_xh + (size_t)token * HDIM;

    float acc[NEXP];
#pragma unroll
    for (int e = 0; e < NEXP; e++) acc[e] = 0.f;

    for (int h = lane; h < HDIM; h += 32) {
        float xv = __ldg(xr + h);
        xh[h] = __float2half_rn(xv);
        float4 g0 = *reinterpret_cast<const float4*>(gw + (size_t)h * NEXP);
        float4 g1 = *reinterpret_cast<const float4*>(gw + (size_t)h * NEXP + 4);
        acc[0] += xv * g0.x;  acc[1] += xv * g0.y;
        acc[2] += xv * g0.z;  acc[3] += xv * g0.w;
        acc[4] += xv * g1.x;  acc[5] += xv * g1.y;
        acc[6] += xv * g1.z;  acc[7] += xv * g1.w;
    }
#pragma unroll
    for (int off = 16; off > 0; off >>= 1)
#pragma unroll
        for (int e = 0; e < NEXP; e++)
            acc[e] += __shfl_xor_sync(0xffffffffu, acc[e], off);

    if (lane == 0) {
        float v0 = -3.4e38f, v1 = -3.4e38f;
        int   i0 = 0,        i1 = 0;
#pragma unroll
        for (int e = 0; e < NEXP; e++) {
            float v = acc[e];
            if (v > v0)      { v1 = v0; i1 = i0; v0 = v; i0 = e; }
            else if (v > v1) { v1 = v;  i1 = e; }
        }
        float p  = expf(v1 - v0);
        float w0 = 1.f / (1.f + p);
        float w1 = p * w0;
        int pos0 = atomicAdd(&g_count[i0], 1);
        int pos1 = atomicAdd(&g_count[i1], 1);
        g_list [i0 * MAX_B + pos0] = token;  g_wlist[i0 * MAX_B + pos0] = w0;
        g_list [i1 * MAX_B + pos1] = token;  g_wlist[i1 * MAX_B + pos1] = w1;
    }
}

// ---------------------------------------------------------------------------
// Warp-MMA grouped GEMM (R8, unchanged). Grid (MAX_B/MT, ODIM/NT, NEXP),
// 128 threads, 2 CTAs/SM. Software-pipelined register loads.
__global__ __launch_bounds__(128, 2)
void moe_mma_kernel(float* __restrict__ out)
{
    extern __shared__ char smem[];
    const int e   = blockIdx.z;
    const int cnt = g_count[e];
    const int m0  = blockIdx.x * MT;
    if (m0 >= cnt) return;
    const int bn0  = blockIdx.y * NT;
    const int tid  = threadIdx.x;
    const int wid  = tid >> 5;
    const int lane = tid & 31;

    const uint32_t sbase = smem_u32(smem);
    int*   s_ent = reinterpret_cast<int*>(smem + SM_ENT);
    float* s_w   = reinterpret_cast<float*>(smem + SM_W);

    if (tid < MT) {
        int m = m0 + tid;
        if (m < cnt) {
            s_ent[tid] = g_list [e * MAX_B + m];
            s_w  [tid] = g_wlist[e * MAX_B + m];
        } else { s_ent[tid] = -1; s_w[tid] = 0.f; }
    }
    __syncthreads();

    // ---- cp.async addressing: A/B each 1024 16B-units -> 8 per thread ----
    size_t   aoff[8]; uint32_t asw[8];
#pragma unroll
    for (int i = 0; i < 8; i++) {
        int g = tid + 128 * i, r = g >> 3, q = g & 7;
        int ent = s_ent[r];
        int tok = ent < 0 ? 0 : ent;
        aoff[i] = (size_t)tok * HDIM + q * 8;
        asw[i]  = SWZ(r * 128 + q * 16);
    }
    size_t   boff[8]; uint32_t bsw[8];
    const size_t eW = (size_t)e * ODIM * HDIM;
#pragma unroll
    for (int i = 0; i < 8; i++) {
        int g = tid + 128 * i, n = g >> 3, q = g & 7;
        boff[i] = eW + (size_t)(bn0 + n) * HDIM + q * 8;
        bsw[i]  = SWZ(n * 128 + q * 16);
    }

    auto fill = [&](int st, int k0) {
        uint32_t sa = sbase + SM_TILES + st * STAGE_BYTES;
#pragma unroll
        for (int i = 0; i < 8; i++) cp_async16(sa + ST_A + asw[i], g_xh  + aoff[i] + k0);
#pragma unroll
        for (int i = 0; i < 8; i++) cp_async16(sa + ST_B + bsw[i], g_whT + boff[i] + k0);
    };

    fill(0, 0);  CP_COMMIT();
    fill(1, KC); CP_COMMIT();

    // ---- warp tiling: 4 warps as 2(m) x 2(n); warp tile 64x64 ----
    const int wm = (wid & 1) * 64;
    const int wn = (wid >> 1) * 64;

    const int rowA = wm + (lane & 15);
    const uint32_t swA = (rowA & 7) << 4;
    const uint32_t aRow = rowA * 128;
    const uint32_t aKsel = (lane >> 4) << 4;          // 0 or 16
    const int rowB = wn + (lane & 7) + ((lane >> 4) & 1) * 8;
    const uint32_t swB = (rowB & 7) << 4;
    const uint32_t bRow = rowB * 128;
    const uint32_t bKsel = ((lane >> 3) & 1) << 4;    // 0 or 16

    float acc[4][8][4];
#pragma unroll
    for (int mi = 0; mi < 4; mi++)
#pragma unroll
        for (int nj = 0; nj < 8; nj++)
#pragma unroll
            for (int q = 0; q < 4; q++) acc[mi][nj][q] = 0.f;

    uint32_t aA[4][4], aB[4][4], bb[2][4];

    int stage = 0;
    int fstage = 2;
    for (int s = 0; s < KSTAGES; s++) {
        CP_WAIT1();
        __syncthreads();
        if (s + 2 < KSTAGES) fill(fstage, (s + 2) * KC);
        CP_COMMIT();
        if (++fstage == NSTAGE) fstage = 0;

        const uint32_t st = sbase + SM_TILES + stage * STAGE_BYTES;
        if (++stage == NSTAGE) stage = 0;

        const uint32_t aBase = st + ST_A + aRow + aKsel;
        const uint32_t bBase = st + ST_B + bRow + bKsel;

#pragma unroll
        for (int mi = 0; mi < 4; mi++)
            ldsm4(aA[mi], (aBase ^ swA) + mi * 2048);
        ldsm4(bb[0], (bBase ^ swB));

#pragma unroll
        for (int c = 0; c < 4; c++) {
            uint32_t (*aCur)[4] = (c & 1) ? aB : aA;
            uint32_t (*aNxt)[4] = (c & 1) ? aA : aB;
#pragma unroll
            for (int njp = 0; njp < 4; njp++) {
                const int cur = njp & 1;
                if (njp < 3) {
                    ldsm4(bb[cur ^ 1],
                          (((c * 32) ^ bBase) ^ swB) + (njp + 1) * 2048);
                } else if (c < 3) {
                    ldsm4(bb[cur ^ 1],
                          ((((c + 1) * 32) ^ bBase) ^ swB));
                }
                if (njp == 1 && c < 3) {
#pragma unroll
                    for (int mi = 0; mi < 4; mi++)
                        ldsm4(aNxt[mi],
                              ((((c + 1) * 32) ^ aBase) ^ swA) + mi * 2048);
                }
#pragma unroll
                for (int mi = 0; mi < 4; mi++) {
                    hmma(acc[mi][2 * njp],     aCur[mi], bb[cur][0], bb[cur][1]);
                    hmma(acc[mi][2 * njp + 1], aCur[mi], bb[cur][2], bb[cur][3]);
                }
            }
        }
    }

    // ---- epilogue: scale + red.global.add.v2 ----
#pragma unroll
    for (int mi = 0; mi < 4; mi++) {
        const int row0 = wm + mi * 16 + (lane >> 2);
#pragma unroll
        for (int hh = 0; hh < 2; hh++) {
            const int r   = row0 + hh * 8;
            const int ent = s_ent[r];
            if (ent < 0) continue;
            const float wt = s_w[r];
            float* base = out + (size_t)ent * ODIM + bn0 + wn + (lane & 3) * 2;
#pragma unroll
            for (int nj = 0; nj < 8; nj++) {
                float v0 = acc[mi][nj][2 * hh]     * wt;
                float v1 = acc[mi][nj][2 * hh + 1] * wt;
                asm volatile("red.global.add.v2.f32 [%0], {%1, %2};"
                             :: "l"(base + nj * 8), "f"(v0), "f"(v1) : "memory");
            }
        }
    }
}

// ---------------------------------------------------------------------------
extern "C" void kernel_launch(void* const* d_in, const int* in_sizes, int n_in,
                              void* d_out, int out_size)
{
    const float* x  = (const float*)d_in[0];
    const float* gw = (const float*)d_in[1];
    const float* ew = (const float*)d_in[2];
    float*       out = (float*)d_out;

    const int B = in_sizes[0] / HDIM;

    cudaMemsetAsync(d_out, 0, (size_t)out_size * sizeof(float));

    void* cnt_ptr = nullptr;
    cudaGetSymbolAddress(&cnt_ptr, g_count);
    cudaMemsetAsync(cnt_ptr, 0, NEXP * sizeof(int));

    prepass_kernel<<<dim3(64, 64, NEXP + 1), 256>>>(x, gw, ew, B);

    cudaFuncSetAttribute(moe_mma_kernel,
                         cudaFuncAttributeMaxDynamicSharedMemorySize, SMEM_TOTAL);
    const int mtiles = (B + MT - 1) / MT;
    moe_mma_kernel<<<dim3(mtiles, ODIM / NT, NEXP), 128, SMEM_TOTAL>>>(out);
}

// round 12
// speedup vs baseline: 1.0280x; 1.0280x over previous
#include <cuda_runtime.h>
#include <cuda_fp16.h>
#include <cstdint>

// ===========================================================================
// MoE (B=8192, H=O=4096, E=8, top-2 softmax), fp16 warp MMA, fp32 accum.
// R12: GEMM = R8 (frozen; ~77% tensor = this path's practical floor).
//      Prepass fused with gating at z=0 (dispatched FIRST) so the
//      latency-bound gating overlaps the DRAM-bound W-convert wave.
// ===========================================================================

#define MAX_B   8192
#define NEXP    8
#define HDIM    4096
#define ODIM    4096

#define MT      128
#define NT      128
#define KC      64
#define KSTAGES (HDIM / KC)     // 64
#define NSTAGE  3

// SMEM layout (GEMM)
#define SM_ENT      0           // 128 ints
#define SM_W        512         // 128 floats
#define SM_TILES    1024
#define ST_A        0           // 16KB
#define ST_B        16384       // 16KB
#define STAGE_BYTES 32768
#define SMEM_TOTAL  (SM_TILES + NSTAGE * STAGE_BYTES)   // 99328

// ---------------------------------------------------------------------------
__device__ int   g_count[NEXP];
__device__ int   g_list [NEXP * MAX_B];
__device__ float g_wlist[NEXP * MAX_B];
__device__ __half g_xh [(size_t)MAX_B * HDIM];
__device__ __half g_whT[(size_t)NEXP * ODIM * HDIM];   // [e][n][k]

// ---------------------------------------------------------------------------
__device__ __forceinline__ uint32_t smem_u32(const void* p) {
    uint32_t a;
    asm("{ .reg .u64 t; cvta.to.shared.u64 t, %1; cvt.u32.u64 %0, t; }"
        : "=r"(a) : "l"(p));
    return a;
}
__device__ __forceinline__ void cp_async16(uint32_t dst, const void* src) {
    asm volatile("cp.async.cg.shared.global [%0], [%1], 16;"
                 :: "r"(dst), "l"(src) : "memory");
}
#define CP_COMMIT() asm volatile("cp.async.commit_group;" ::: "memory")
#define CP_WAIT1()  asm volatile("cp.async.wait_group 1;" ::: "memory")

#define SWZ(x) ((x) ^ (((x) >> 3) & 0x70))

__device__ __forceinline__ void ldsm4(uint32_t r[4], uint32_t addr) {
    asm volatile("ldmatrix.sync.aligned.m8n8.x4.shared.b16 {%0,%1,%2,%3}, [%4];"
                 : "=r"(r[0]), "=r"(r[1]), "=r"(r[2]), "=r"(r[3]) : "r"(addr));
}
__device__ __forceinline__ void hmma(float c[4], const uint32_t a[4],
                                     uint32_t b0, uint32_t b1) {
    asm volatile(
        "mma.sync.aligned.m16n8k16.row.col.f32.f16.f16.f32 "
        "{%0,%1,%2,%3}, {%4,%5,%6,%7}, {%8,%9}, {%0,%1,%2,%3};"
        : "+f"(c[0]), "+f"(c[1]), "+f"(c[2]), "+f"(c[3])
        : "r"(a[0]), "r"(a[1]), "r"(a[2]), "r"(a[3]), "r"(b0), "r"(b1));
}

// ---------------------------------------------------------------------------
// Fused pre-pass. Grid (64, 64, 9), 256 threads.
//   z == 0:      gating (blocks with flat id < B/8), fused x -> fp16
//   z in [1,9):  W[e=z-1][k][n] fp32 -> g_whT[e][n][k] fp16 (64k x 64n tile)
// Gating is in the FIRST z-plane so its latency-bound blocks are dispatched
// before (and overlap with) the DRAM-bound convert wave.
__global__ __launch_bounds__(256)
void prepass_kernel(const float* __restrict__ x,
                    const float* __restrict__ gw,
                    const float* __restrict__ W, int B)
{
    __shared__ float tile[64][65];
    const int tid = threadIdx.x;

    if (blockIdx.z > 0) {
        // ---------------- convert_w (identical math to R10/R11) -------------
        const int n0 = blockIdx.x * 64;
        const int k0 = blockIdx.y * 64;
        const size_t eoff = (size_t)(blockIdx.z - 1) * HDIM * ODIM;

#pragma unroll
        for (int rep = 0; rep < 4; rep++) {
            int idx = rep * 256 + tid;
            int kr = idx >> 4, c = idx & 15;
            float4 v = *reinterpret_cast<const float4*>(
                W + eoff + (size_t)(k0 + kr) * ODIM + n0 + c * 4);
            tile[kr][c * 4 + 0] = v.x;
            tile[kr][c * 4 + 1] = v.y;
            tile[kr][c * 4 + 2] = v.z;
            tile[kr][c * 4 + 3] = v.w;
        }
        __syncthreads();

        const int u = tid & 7;
#pragma unroll
        for (int rep = 0; rep < 2; rep++) {
            int n = (tid >> 3) + rep * 32;
            __half2 h[4];
#pragma unroll
            for (int j = 0; j < 4; j++) {
                float v0 = tile[u * 8 + 2 * j][n];
                float v1 = tile[u * 8 + 2 * j + 1][n];
                h[j] = __floats2half2_rn(v0, v1);
            }
            *reinterpret_cast<uint4*>(
                g_whT + eoff + (size_t)(n0 + n) * HDIM + k0 + u * 8)
                = *reinterpret_cast<uint4*>(h);
        }
        return;
    }

    // ---------------- gating (identical math/order since R5) ---------------
    const int blk = blockIdx.x + blockIdx.y * 64;     // flat block id
    if (blk >= (B + 7) / 8) return;

    const int warp  = tid >> 5;
    const int lane  = tid & 31;
    const int token = blk * 8 + warp;
    if (token >= B) return;

    const float* xr = x + (size_t)token * HDIM;
    __half* xh = g_xh + (size_t)token * HDIM;

    float acc[NEXP];
#pragma unroll
    for (int e = 0; e < NEXP; e++) acc[e] = 0.f;

    for (int h = lane; h < HDIM; h += 32) {
        float xv = __ldg(xr + h);
        xh[h] = __float2half_rn(xv);
        float4 g0 = *reinterpret_cast<const float4*>(gw + (size_t)h * NEXP);
        float4 g1 = *reinterpret_cast<const float4*>(gw + (size_t)h * NEXP + 4);
        acc[0] += xv * g0.x;  acc[1] += xv * g0.y;
        acc[2] += xv * g0.z;  acc[3] += xv * g0.w;
        acc[4] += xv * g1.x;  acc[5] += xv * g1.y;
        acc[6] += xv * g1.z;  acc[7] += xv * g1.w;
    }
#pragma unroll
    for (int off = 16; off > 0; off >>= 1)
#pragma unroll
        for (int e = 0; e < NEXP; e++)
            acc[e] += __shfl_xor_sync(0xffffffffu, acc[e], off);

    if (lane == 0) {
        float v0 = -3.4e38f, v1 = -3.4e38f;
        int   i0 = 0,        i1 = 0;
#pragma unroll
        for (int e = 0; e < NEXP; e++) {
            float v = acc[e];
            if (v > v0)      { v1 = v0; i1 = i0; v0 = v; i0 = e; }
            else if (v > v1) { v1 = v;  i1 = e; }
        }
        float p  = expf(v1 - v0);
        float w0 = 1.f / (1.f + p);
        float w1 = p * w0;
        int pos0 = atomicAdd(&g_count[i0], 1);
        int pos1 = atomicAdd(&g_count[i1], 1);
        g_list [i0 * MAX_B + pos0] = token;  g_wlist[i0 * MAX_B + pos0] = w0;
        g_list [i1 * MAX_B + pos1] = token;  g_wlist[i1 * MAX_B + pos1] = w1;
    }
}

// ---------------------------------------------------------------------------
// Warp-MMA grouped GEMM (R8, frozen). Grid (MAX_B/MT, ODIM/NT, NEXP),
// 128 threads, 2 CTAs/SM. Software-pipelined register loads.
__global__ __launch_bounds__(128, 2)
void moe_mma_kernel(float* __restrict__ out)
{
    extern __shared__ char smem[];
    const int e   = blockIdx.z;
    const int cnt = g_count[e];
    const int m0  = blockIdx.x * MT;
    if (m0 >= cnt) return;
    const int bn0  = blockIdx.y * NT;
    const int tid  = threadIdx.x;
    const int wid  = tid >> 5;
    const int lane = tid & 31;

    const uint32_t sbase = smem_u32(smem);
    int*   s_ent = reinterpret_cast<int*>(smem + SM_ENT);
    float* s_w   = reinterpret_cast<float*>(smem + SM_W);

    if (tid < MT) {
        int m = m0 + tid;
        if (m < cnt) {
            s_ent[tid] = g_list [e * MAX_B + m];
            s_w  [tid] = g_wlist[e * MAX_B + m];
        } else { s_ent[tid] = -1; s_w[tid] = 0.f; }
    }
    __syncthreads();

    // ---- cp.async addressing: A/B each 1024 16B-units -> 8 per thread ----
    size_t   aoff[8]; uint32_t asw[8];
#pragma unroll
    for (int i = 0; i < 8; i++) {
        int g = tid + 128 * i, r = g >> 3, q = g & 7;
        int ent = s_ent[r];
        int tok = ent < 0 ? 0 : ent;
        aoff[i] = (size_t)tok * HDIM + q * 8;
        asw[i]  = SWZ(r * 128 + q * 16);
    }
    size_t   boff[8]; uint32_t bsw[8];
    const size_t eW = (size_t)e * ODIM * HDIM;
#pragma unroll
    for (int i = 0; i < 8; i++) {
        int g = tid + 128 * i, n = g >> 3, q = g & 7;
        boff[i] = eW + (size_t)(bn0 + n) * HDIM + q * 8;
        bsw[i]  = SWZ(n * 128 + q * 16);
    }

    auto fill = [&](int st, int k0) {
        uint32_t sa = sbase + SM_TILES + st * STAGE_BYTES;
#pragma unroll
        for (int i = 0; i < 8; i++) cp_async16(sa + ST_A + asw[i], g_xh  + aoff[i] + k0);
#pragma unroll
        for (int i = 0; i < 8; i++) cp_async16(sa + ST_B + bsw[i], g_whT + boff[i] + k0);
    };

    fill(0, 0);  CP_COMMIT();
    fill(1, KC); CP_COMMIT();

    // ---- warp tiling: 4 warps as 2(m) x 2(n); warp tile 64x64 ----
    const int wm = (wid & 1) * 64;
    const int wn = (wid >> 1) * 64;

    const int rowA = wm + (lane & 15);
    const uint32_t swA = (rowA & 7) << 4;
    const uint32_t aRow = rowA * 128;
    const uint32_t aKsel = (lane >> 4) << 4;          // 0 or 16
    const int rowB = wn + (lane & 7) + ((lane >> 4) & 1) * 8;
    const uint32_t swB = (rowB & 7) << 4;
    const uint32_t bRow = rowB * 128;
    const uint32_t bKsel = ((lane >> 3) & 1) << 4;    // 0 or 16

    float acc[4][8][4];
#pragma unroll
    for (int mi = 0; mi < 4; mi++)
#pragma unroll
        for (int nj = 0; nj < 8; nj++)
#pragma unroll
            for (int q = 0; q < 4; q++) acc[mi][nj][q] = 0.f;

    uint32_t aA[4][4], aB[4][4], bb[2][4];

    int stage = 0;
    int fstage = 2;
    for (int s = 0; s < KSTAGES; s++) {
        CP_WAIT1();
        __syncthreads();
        if (s + 2 < KSTAGES) fill(fstage, (s + 2) * KC);
        CP_COMMIT();
        if (++fstage == NSTAGE) fstage = 0;

        const uint32_t st = sbase + SM_TILES + stage * STAGE_BYTES;
        if (++stage == NSTAGE) stage = 0;

        const uint32_t aBase = st + ST_A + aRow + aKsel;
        const uint32_t bBase = st + ST_B + bRow + bKsel;

#pragma unroll
        for (int mi = 0; mi < 4; mi++)
            ldsm4(aA[mi], (aBase ^ swA) + mi * 2048);
        ldsm4(bb[0], (bBase ^ swB));

#pragma unroll
        for (int c = 0; c < 4; c++) {
            uint32_t (*aCur)[4] = (c & 1) ? aB : aA;
            uint32_t (*aNxt)[4] = (c & 1) ? aA : aB;
#pragma unroll
            for (int njp = 0; njp < 4; njp++) {
                const int cur = njp & 1;
                if (njp < 3) {
                    ldsm4(bb[cur ^ 1],
                          (((c * 32) ^ bBase) ^ swB) + (njp + 1) * 2048);
                } else if (c < 3) {
                    ldsm4(bb[cur ^ 1],
                          ((((c + 1) * 32) ^ bBase) ^ swB));
                }
                if (njp == 1 && c < 3) {
#pragma unroll
                    for (int mi = 0; mi < 4; mi++)
                        ldsm4(aNxt[mi],
                              ((((c + 1) * 32) ^ aBase) ^ swA) + mi * 2048);
                }
#pragma unroll
                for (int mi = 0; mi < 4; mi++) {
                    hmma(acc[mi][2 * njp],     aCur[mi], bb[cur][0], bb[cur][1]);
                    hmma(acc[mi][2 * njp + 1], aCur[mi], bb[cur][2], bb[cur][3]);
                }
            }
        }
    }

    // ---- epilogue: scale + red.global.add.v2 ----
#pragma unroll
    for (int mi = 0; mi < 4; mi++) {
        const int row0 = wm + mi * 16 + (lane >> 2);
#pragma unroll
        for (int hh = 0; hh < 2; hh++) {
            const int r   = row0 + hh * 8;
            const int ent = s_ent[r];
            if (ent < 0) continue;
            const float wt = s_w[r];
            float* base = out + (size_t)ent * ODIM + bn0 + wn + (lane & 3) * 2;
#pragma unroll
            for (int nj = 0; nj < 8; nj++) {
                float v0 = acc[mi][nj][2 * hh]     * wt;
                float v1 = acc[mi][nj][2 * hh + 1] * wt;
                asm volatile("red.global.add.v2.f32 [%0], {%1, %2};"
                             :: "l"(base + nj * 8), "f"(v0), "f"(v1) : "memory");
            }
        }
    }
}

// ---------------------------------------------------------------------------
extern "C" void kernel_launch(void* const* d_in, const int* in_sizes, int n_in,
                              void* d_out, int out_size)
{
    const float* x  = (const float*)d_in[0];
    const float* gw = (const float*)d_in[1];
    const float* ew = (const float*)d_in[2];
    float*       out = (float*)d_out;

    const int B = in_sizes[0] / HDIM;

    cudaMemsetAsync(d_out, 0, (size_t)out_size * sizeof(float));

    void* cnt_ptr = nullptr;
    cudaGetSymbolAddress(&cnt_ptr, g_count);
    cudaMemsetAsync(cnt_ptr, 0, NEXP * sizeof(int));

    prepass_kernel<<<dim3(64, 64, NEXP + 1), 256>>>(x, gw, ew, B);

    cudaFuncSetAttribute(moe_mma_kernel,
                         cudaFuncAttributeMaxDynamicSharedMemorySize, SMEM_TOTAL);
    const int mtiles = (B + MT - 1) / MT;
    moe_mma_kernel<<<dim3(mtiles, ODIM / NT, NEXP), 128, SMEM_TOTAL>>>(out);
}

// round 15
// speedup vs baseline: 1.0364x; 1.0081x over previous
#include <cuda_runtime.h>
#include <cuda_fp16.h>
#include <cstdint>

// ===========================================================================
// MoE (B=8192, H=O=4096, E=8, top-2 softmax), fp16 warp MMA, fp32 accum.
// R15: identical to R14 (infra failure last round — never ran).
//      R13's out-zeroing coverage bug fixed: z=9 plane writes
//      2048 uint4/block * 4096 blocks = full B*ODIM buffer.
//      Prepass grid (64,64,10): z=0 gating (first), z=1..8 W convert,
//      z=9 zero out. GEMM = R8 (frozen; ~77% tensor = mma.sync floor).
// ===========================================================================

#define MAX_B   8192
#define NEXP    8
#define HDIM    4096
#define ODIM    4096

#define MT      128
#define NT      128
#define KC      64
#define KSTAGES (HDIM / KC)     // 64
#define NSTAGE  3

// SMEM layout (GEMM)
#define SM_ENT      0           // 128 ints
#define SM_W        512         // 128 floats
#define SM_TILES    1024
#define ST_A        0           // 16KB
#define ST_B        16384       // 16KB
#define STAGE_BYTES 32768
#define SMEM_TOTAL  (SM_TILES + NSTAGE * STAGE_BYTES)   // 99328

// ---------------------------------------------------------------------------
__device__ int   g_count[NEXP];
__device__ int   g_list [NEXP * MAX_B];
__device__ float g_wlist[NEXP * MAX_B];
__device__ __half g_xh [(size_t)MAX_B * HDIM];
__device__ __half g_whT[(size_t)NEXP * ODIM * HDIM];   // [e][n][k]

// ---------------------------------------------------------------------------
__device__ __forceinline__ uint32_t smem_u32(const void* p) {
    uint32_t a;
    asm("{ .reg .u64 t; cvta.to.shared.u64 t, %1; cvt.u32.u64 %0, t; }"
        : "=r"(a) : "l"(p));
    return a;
}
__device__ __forceinline__ void cp_async16(uint32_t dst, const void* src) {
    asm volatile("cp.async.cg.shared.global [%0], [%1], 16;"
                 :: "r"(dst), "l"(src) : "memory");
}
#define CP_COMMIT() asm volatile("cp.async.commit_group;" ::: "memory")
#define CP_WAIT1()  asm volatile("cp.async.wait_group 1;" ::: "memory")

#define SWZ(x) ((x) ^ (((x) >> 3) & 0x70))

__device__ __forceinline__ void ldsm4(uint32_t r[4], uint32_t addr) {
    asm volatile("ldmatrix.sync.aligned.m8n8.x4.shared.b16 {%0,%1,%2,%3}, [%4];"
                 : "=r"(r[0]), "=r"(r[1]), "=r"(r[2]), "=r"(r[3]) : "r"(addr));
}
__device__ __forceinline__ void hmma(float c[4], const uint32_t a[4],
                                     uint32_t b0, uint32_t b1) {
    asm volatile(
        "mma.sync.aligned.m16n8k16.row.col.f32.f16.f16.f32 "
        "{%0,%1,%2,%3}, {%4,%5,%6,%7}, {%8,%9}, {%0,%1,%2,%3};"
        : "+f"(c[0]), "+f"(c[1]), "+f"(c[2]), "+f"(c[3])
        : "r"(a[0]), "r"(a[1]), "r"(a[2]), "r"(a[3]), "r"(b0), "r"(b1));
}

// ---------------------------------------------------------------------------
// Fused pre-pass. Grid (64, 64, 10), 256 threads.
__global__ __launch_bounds__(256)
void prepass_kernel(const float* __restrict__ x,
                    const float* __restrict__ gw,
                    const float* __restrict__ W,
                    float* __restrict__ out, int B)
{
    __shared__ float tile[64][65];
    const int tid = threadIdx.x;

    if (blockIdx.z >= 1 && blockIdx.z <= NEXP) {
        // ---------------- convert_w (identical math since R10) --------------
        const int n0 = blockIdx.x * 64;
        const int k0 = blockIdx.y * 64;
        const size_t eoff = (size_t)(blockIdx.z - 1) * HDIM * ODIM;

#pragma unroll
        for (int rep = 0; rep < 4; rep++) {
            int idx = rep * 256 + tid;
            int kr = idx >> 4, c = idx & 15;
            float4 v = *reinterpret_cast<const float4*>(
                W + eoff + (size_t)(k0 + kr) * ODIM + n0 + c * 4);
            tile[kr][c * 4 + 0] = v.x;
            tile[kr][c * 4 + 1] = v.y;
            tile[kr][c * 4 + 2] = v.z;
            tile[kr][c * 4 + 3] = v.w;
        }
        __syncthreads();

        const int u = tid & 7;
#pragma unroll
        for (int rep = 0; rep < 2; rep++) {
            int n = (tid >> 3) + rep * 32;
            __half2 h[4];
#pragma unroll
            for (int j = 0; j < 4; j++) {
                float v0 = tile[u * 8 + 2 * j][n];
                float v1 = tile[u * 8 + 2 * j + 1][n];
                h[j] = __floats2half2_rn(v0, v1);
            }
            *reinterpret_cast<uint4*>(
                g_whT + eoff + (size_t)(n0 + n) * HDIM + k0 + u * 8)
                = *reinterpret_cast<uint4*>(h);
        }
        return;
    }

    if (blockIdx.z == NEXP + 1) {
        // ---------------- zero 'out' (folded memset, FULL coverage) ---------
        // total uint4 = B*ODIM/4 = 8,388,608; 4096 blocks * 2048 = exact.
        const int blk = blockIdx.x + blockIdx.y * 64;      // 0..4095
        const size_t total4 = (size_t)B * ODIM / 4;
        uint4* o4 = reinterpret_cast<uint4*>(out);
        const uint4 z = make_uint4(0u, 0u, 0u, 0u);
        size_t base = (size_t)blk * 2048;
#pragma unroll
        for (int rep = 0; rep < 8; rep++) {
            size_t idx = base + rep * 256 + tid;
            if (idx < total4) o4[idx] = z;
        }
        return;
    }

    // ---------------- gating (z == 0; identical math/order since R5) -------
    const int blk = blockIdx.x + blockIdx.y * 64;     // flat block id
    if (blk >= (B + 7) / 8) return;

    const int warp  = tid >> 5;
    const int lane  = tid & 31;
    const int token = blk * 8 + warp;
    if (token >= B) return;

    const float* xr = x + (size_t)token * HDIM;
    __half* xh = g_xh + (size_t)token * HDIM;

    float acc[NEXP];
#pragma unroll
    for (int e = 0; e < NEXP; e++) acc[e] = 0.f;

    for (int h = lane; h < HDIM; h += 32) {
        float xv = __ldg(xr + h);
        xh[h] = __float2half_rn(xv);
        float4 g0 = *reinterpret_cast<const float4*>(gw + (size_t)h * NEXP);
        float4 g1 = *reinterpret_cast<const float4*>(gw + (size_t)h * NEXP + 4);
        acc[0] += xv * g0.x;  acc[1] += xv * g0.y;
        acc[2] += xv * g0.z;  acc[3] += xv * g0.w;
        acc[4] += xv * g1.x;  acc[5] += xv * g1.y;
        acc[6] += xv * g1.z;  acc[7] += xv * g1.w;
    }
#pragma unroll
    for (int off = 16; off > 0; off >>= 1)
#pragma unroll
        for (int e = 0; e < NEXP; e++)
            acc[e] += __shfl_xor_sync(0xffffffffu, acc[e], off);

    if (lane == 0) {
        float v0 = -3.4e38f, v1 = -3.4e38f;
        int   i0 = 0,        i1 = 0;
#pragma unroll
        for (int e = 0; e < NEXP; e++) {
            float v = acc[e];
            if (v > v0)      { v1 = v0; i1 = i0; v0 = v; i0 = e; }
            else if (v > v1) { v1 = v;  i1 = e; }
        }
        float p  = expf(v1 - v0);
        float w0 = 1.f / (1.f + p);
        float w1 = p * w0;
        int pos0 = atomicAdd(&g_count[i0], 1);
        int pos1 = atomicAdd(&g_count[i1], 1);
        g_list [i0 * MAX_B + pos0] = token;  g_wlist[i0 * MAX_B + pos0] = w0;
        g_list [i1 * MAX_B + pos1] = token;  g_wlist[i1 * MAX_B + pos1] = w1;
    }
}

// ---------------------------------------------------------------------------
// Warp-MMA grouped GEMM (R8, frozen). Grid (MAX_B/MT, ODIM/NT, NEXP),
// 128 threads, 2 CTAs/SM. Software-pipelined register loads.
__global__ __launch_bounds__(128, 2)
void moe_mma_kernel(float* __restrict__ out)
{
    extern __shared__ char smem[];
    const int e   = blockIdx.z;
    const int cnt = g_count[e];
    const int m0  = blockIdx.x * MT;
    if (m0 >= cnt) return;
    const int bn0  = blockIdx.y * NT;
    const int tid  = threadIdx.x;
    const int wid  = tid >> 5;
    const int lane = tid & 31;

    const uint32_t sbase = smem_u32(smem);
    int*   s_ent = reinterpret_cast<int*>(smem + SM_ENT);
    float* s_w   = reinterpret_cast<float*>(smem + SM_W);

    if (tid < MT) {
        int m = m0 + tid;
        if (m < cnt) {
            s_ent[tid] = g_list [e * MAX_B + m];
            s_w  [tid] = g_wlist[e * MAX_B + m];
        } else { s_ent[tid] = -1; s_w[tid] = 0.f; }
    }
    __syncthreads();

    // ---- cp.async addressing: A/B each 1024 16B-units -> 8 per thread ----
    size_t   aoff[8]; uint32_t asw[8];
#pragma unroll
    for (int i = 0; i < 8; i++) {
        int g = tid + 128 * i, r = g >> 3, q = g & 7;
        int ent = s_ent[r];
        int tok = ent < 0 ? 0 : ent;
        aoff[i] = (size_t)tok * HDIM + q * 8;
        asw[i]  = SWZ(r * 128 + q * 16);
    }
    size_t   boff[8]; uint32_t bsw[8];
    const size_t eW = (size_t)e * ODIM * HDIM;
#pragma unroll
    for (int i = 0; i < 8; i++) {
        int g = tid + 128 * i, n = g >> 3, q = g & 7;
        boff[i] = eW + (size_t)(bn0 + n) * HDIM + q * 8;
        bsw[i]  = SWZ(n * 128 + q * 16);
    }

    auto fill = [&](int st, int k0) {
        uint32_t sa = sbase + SM_TILES + st * STAGE_BYTES;
#pragma unroll
        for (int i = 0; i < 8; i++) cp_async16(sa + ST_A + asw[i], g_xh  + aoff[i] + k0);
#pragma unroll
        for (int i = 0; i < 8; i++) cp_async16(sa + ST_B + bsw[i], g_whT + boff[i] + k0);
    };

    fill(0, 0);  CP_COMMIT();
    fill(1, KC); CP_COMMIT();

    // ---- warp tiling: 4 warps as 2(m) x 2(n); warp tile 64x64 ----
    const int wm = (wid & 1) * 64;
    const int wn = (wid >> 1) * 64;

    const int rowA = wm + (lane & 15);
    const uint32_t swA = (rowA & 7) << 4;
    const uint32_t aRow = rowA * 128;
    const uint32_t aKsel = (lane >> 4) << 4;          // 0 or 16
    const int rowB = wn + (lane & 7) + ((lane >> 4) & 1) * 8;
    const uint32_t swB = (rowB & 7) << 4;
    const uint32_t bRow = rowB * 128;
    const uint32_t bKsel = ((lane >> 3) & 1) << 4;    // 0 or 16

    float acc[4][8][4];
#pragma unroll
    for (int mi = 0; mi < 4; mi++)
#pragma unroll
        for (int nj = 0; nj < 8; nj++)
#pragma unroll
            for (int q = 0; q < 4; q++) acc[mi][nj][q] = 0.f;

    uint32_t aA[4][4], aB[4][4], bb[2][4];

    int stage = 0;
    int fstage = 2;
    for (int s = 0; s < KSTAGES; s++) {
        CP_WAIT1();
        __syncthreads();
        if (s + 2 < KSTAGES) fill(fstage, (s + 2) * KC);
        CP_COMMIT();
        if (++fstage == NSTAGE) fstage = 0;

        const uint32_t st = sbase + SM_TILES + stage * STAGE_BYTES;
        if (++stage == NSTAGE) stage = 0;

        const uint32_t aBase = st + ST_A + aRow + aKsel;
        const uint32_t bBase = st + ST_B + bRow + bKsel;

#pragma unroll
        for (int mi = 0; mi < 4; mi++)
            ldsm4(aA[mi], (aBase ^ swA) + mi * 2048);
        ldsm4(bb[0], (bBase ^ swB));

#pragma unroll
        for (int c = 0; c < 4; c++) {
            uint32_t (*aCur)[4] = (c & 1) ? aB : aA;
            uint32_t (*aNxt)[4] = (c & 1) ? aA : aB;
#pragma unroll
            for (int njp = 0; njp < 4; njp++) {
                const int cur = njp & 1;
                if (njp < 3) {
                    ldsm4(bb[cur ^ 1],
                          (((c * 32) ^ bBase) ^ swB) + (njp + 1) * 2048);
                } else if (c < 3) {
                    ldsm4(bb[cur ^ 1],
                          ((((c + 1) * 32) ^ bBase) ^ swB));
                }
                if (njp == 1 && c < 3) {
#pragma unroll
                    for (int mi = 0; mi < 4; mi++)
                        ldsm4(aNxt[mi],
                              ((((c + 1) * 32) ^ aBase) ^ swA) + mi * 2048);
                }
#pragma unroll
                for (int mi = 0; mi < 4; mi++) {
                    hmma(acc[mi][2 * njp],     aCur[mi], bb[cur][0], bb[cur][1]);
                    hmma(acc[mi][2 * njp + 1], aCur[mi], bb[cur][2], bb[cur][3]);
                }
            }
        }
    }

    // ---- epilogue: scale + red.global.add.v2 ----
#pragma unroll
    for (int mi = 0; mi < 4; mi++) {
        const int row0 = wm + mi * 16 + (lane >> 2);
#pragma unroll
        for (int hh = 0; hh < 2; hh++) {
            const int r   = row0 + hh * 8;
            const int ent = s_ent[r];
            if (ent < 0) continue;
            const float wt = s_w[r];
            float* base = out + (size_t)ent * ODIM + bn0 + wn + (lane & 3) * 2;
#pragma unroll
            for (int nj = 0; nj < 8; nj++) {
                float v0 = acc[mi][nj][2 * hh]     * wt;
                float v1 = acc[mi][nj][2 * hh + 1] * wt;
                asm volatile("red.global.add.v2.f32 [%0], {%1, %2};"
                             :: "l"(base + nj * 8), "f"(v0), "f"(v1) : "memory");
            }
        }
    }
}

// ---------------------------------------------------------------------------
extern "C" void kernel_launch(void* const* d_in, const int* in_sizes, int n_in,
                              void* d_out, int out_size)
{
    const float* x  = (const float*)d_in[0];
    const float* gw = (const float*)d_in[1];
    const float* ew = (const float*)d_in[2];
    float*       out = (float*)d_out;

    const int B = in_sizes[0] / HDIM;

    void* cnt_ptr = nullptr;
    cudaGetSymbolAddress(&cnt_ptr, g_count);
    cudaMemsetAsync(cnt_ptr, 0, NEXP * sizeof(int));

    // z=0: gating; z=1..8: W convert; z=9: zero out (full coverage)
    prepass_kernel<<<dim3(64, 64, NEXP + 2), 256>>>(x, gw, ew, out, B);

    cudaFuncSetAttribute(moe_mma_kernel,
                         cudaFuncAttributeMaxDynamicSharedMemorySize, SMEM_TOTAL);
    const int mtiles = (B + MT - 1) / MT;
    moe_mma_kernel<<<dim3(mtiles, ODIM / NT, NEXP), 128, SMEM_TOTAL>>>(out);
}